// round 6
// baseline (speedup 1.0000x reference)
#include <cuda_runtime.h>
#include <math.h>

#define ROWLEN 1152
#define TR 4
#define NT 128

// ---------------------------------------------------------------------------
// Wigner-3j (real basis, e3nn phase convention) computed on device at launch.
// Layout: per-instruction dense [di,dj,dk], offsets below. Total 363 floats.
// ---------------------------------------------------------------------------
__device__ float g_w3j[363];

__device__ __forceinline__ double dfact(int n) {
    double r = 1.0;
    for (int i = 2; i <= n; i++) r *= (double)i;
    return r;
}

__device__ double cg_racah(int j1, int m1, int j2, int m2, int j3, int m3) {
    if (m1 + m2 != m3) return 0.0;
    double pre = sqrt((2.0 * j3 + 1.0) * dfact(j3 + j1 - j2) * dfact(j3 - j1 + j2) *
                      dfact(j1 + j2 - j3) / dfact(j1 + j2 + j3 + 1));
    pre *= sqrt(dfact(j3 + m3) * dfact(j3 - m3) * dfact(j1 - m1) * dfact(j1 + m1) *
                dfact(j2 - m2) * dfact(j2 + m2));
    double s = 0.0;
    for (int k = 0; k <= j1 + j2 - j3; k++) {
        int d0 = k, d1 = j1 + j2 - j3 - k, d2 = j1 - m1 - k, d3 = j2 + m2 - k;
        int d4 = j3 - j2 + m1 + k, d5 = j3 - j1 - m2 + k;
        if (d0 < 0 || d1 < 0 || d2 < 0 || d3 < 0 || d4 < 0 || d5 < 0) continue;
        s += ((k & 1) ? -1.0 : 1.0) /
             (dfact(d0) * dfact(d1) * dfact(d2) * dfact(d3) * dfact(d4) * dfact(d5));
    }
    return pre * s;
}

// Row x of the complex->real change-of-basis Q(l). Returns #nonzero cols (<=2).
__device__ int qrow(int l, int x, int* col, double* qre, double* qim) {
    const double s = 0.70710678118654752440;
    if (x == l) { col[0] = l; qre[0] = 1.0; qim[0] = 0.0; return 1; }
    if (x > l) {
        int m = x - l;
        col[0] = l - m; qre[0] = s;                 qim[0] = 0.0;
        col[1] = l + m; qre[1] = (m & 1) ? -s : s;  qim[1] = 0.0;
        return 2;
    }
    int m = l - x;
    col[0] = l - m; qre[0] = 0.0; qim[0] = s;
    col[1] = l + m; qre[1] = 0.0; qim[1] = (m & 1) ? s : -s;  // -i*(-1)^m/sqrt2
    return 2;
}

__global__ void w3j_init_kernel() {
    __shared__ double WS[11][384];
    int t = threadIdx.x;
    if (t >= 11) return;
    const int L1[11] = {0,0,0,1,1,1,1,2,2,2,2};
    const int L2[11] = {0,1,2,0,1,1,2,0,1,2,2};
    const int L3[11] = {0,1,2,1,0,2,1,2,1,0,2};
    const int OFF[11] = {0,1,10,35,44,53,98,143,168,213,238};
    int l1 = L1[t], l2 = L2[t], l3 = L3[t];
    int d1 = 2*l1+1, d2 = 2*l2+1, d3 = 2*l3+1;
    double* Wc  = WS[t];
    double* Wre = Wc + 125;
    double* Wim = Wre + 125;
    for (int i = 0; i < 125; i++) Wc[i] = 0.0;

    // complex w3j (purely real values)
    for (int m1 = -l1; m1 <= l1; m1++)
        for (int m2 = -l2; m2 <= l2; m2++) {
            int m3 = -(m1 + m2);
            if (m3 < -l3 || m3 > l3) continue;
            int e = l1 - l2 - m3;
            double par = (((e % 2) + 2) % 2) ? -1.0 : 1.0;
            Wc[((m1 + l1) * d2 + (m2 + l2)) * d3 + (m3 + l3)] =
                par / sqrt(2.0 * l3 + 1.0) * cg_racah(l1, m1, l2, m2, l3, -m3);
        }

    // real basis: W[x,y,z] = sum_{a,b,c} Q1[x,a] Q2[y,b] Q3[z,c] Wc[a,b,c]
    for (int x = 0; x < d1; x++) {
        int ca[2]; double ar[2], ai[2]; int na = qrow(l1, x, ca, ar, ai);
        for (int y = 0; y < d2; y++) {
            int cb[2]; double br[2], bi[2]; int nb = qrow(l2, y, cb, br, bi);
            for (int z = 0; z < d3; z++) {
                int cc[2]; double cr[2], ci[2]; int nc = qrow(l3, z, cc, cr, ci);
                double sr = 0.0, si = 0.0;
                for (int ia = 0; ia < na; ia++)
                    for (int ib = 0; ib < nb; ib++) {
                        double pre = ar[ia]*br[ib] - ai[ia]*bi[ib];
                        double pim = ar[ia]*bi[ib] + ai[ia]*br[ib];
                        for (int ic = 0; ic < nc; ic++) {
                            double wc = Wc[(ca[ia]*d2 + cb[ib])*d3 + cc[ic]];
                            if (wc == 0.0) continue;
                            double qre = pre*cr[ic] - pim*ci[ic];
                            double qim = pre*ci[ic] + pim*cr[ic];
                            sr += qre * wc;
                            si += qim * wc;
                        }
                    }
                Wre[(x*d2 + y)*d3 + z] = sr;
                Wim[(x*d2 + y)*d3 + z] = si;
            }
        }
    }

    // Phase normalization: divide by phase of the max-abs element.
    // For the one tensor with sign-mixed ties at the max magnitude, (2,2,2),
    // numpy's argmax (fp-noise tie-break) selects the d0*d0*d0 diagonal entry
    // (flat 62); pin the phase reference there. All other tensors have either
    // a unique max or same-sign ties, so first-max is unambiguous.
    int n = d1 * d2 * d3;
    int idx;
    if (l1 == 2 && l2 == 2 && l3 == 2) {
        idx = (2 * d2 + 2) * d3 + 2;  // flat 62
    } else {
        double M = 0.0;
        for (int i = 0; i < n; i++) {
            double h = sqrt(Wre[i]*Wre[i] + Wim[i]*Wim[i]);
            if (h > M) M = h;
        }
        idx = 0;
        for (int i = 0; i < n; i++) {
            double h = sqrt(Wre[i]*Wre[i] + Wim[i]*Wim[i]);
            if (h >= M * (1.0 - 1e-9)) { idx = i; break; }
        }
    }
    double h = sqrt(Wre[idx]*Wre[idx] + Wim[idx]*Wim[idx]);
    double pr = Wre[idx] / h, pi = Wim[idx] / h;
    for (int i = 0; i < n; i++)
        g_w3j[OFF[t] + i] = (float)(Wre[i]*pr + Wim[i]*pi);  // W * conj(phase), real part
}

// ---------------------------------------------------------------------------
// Fused main kernel: linL/linR -> TP -> linP -> e3norm -> +old_fii
// One CTA = 128 threads, TR=4 rows. All intermediates in smem.
// ---------------------------------------------------------------------------

template <int DIM, int OFFE>
__device__ __forceinline__ void lin_lr(const float* __restrict__ WL,
                                       const float* __restrict__ WR,
                                       const float* __restrict__ bL,
                                       const float* __restrict__ bR,
                                       const float* A, float* Bf, float* Cf, int tid) {
    float aL[TR][DIM], aR[TR][DIM];
#pragma unroll
    for (int r = 0; r < TR; r++)
#pragma unroll
        for (int i = 0; i < DIM; i++) { aL[r][i] = 0.f; aR[r][i] = 0.f; }
#pragma unroll 2
    for (int u = 0; u < 128; u++) {
        float wl = __ldg(WL + u * 128 + tid);
        float wr = __ldg(WR + u * 128 + tid);
#pragma unroll
        for (int r = 0; r < TR; r++)
#pragma unroll
            for (int i = 0; i < DIM; i++) {
                float xv = A[r * ROWLEN + OFFE + u * DIM + i];
                aL[r][i] = fmaf(xv, wl, aL[r][i]);
                aR[r][i] = fmaf(xv, wr, aR[r][i]);
            }
    }
    const float s = 0.08838834764831845f;  // 1/sqrt(128)
    float bl = (DIM == 1) ? bL[tid] : 0.f;
    float brr = (DIM == 1) ? bR[tid] : 0.f;
#pragma unroll
    for (int r = 0; r < TR; r++)
#pragma unroll
        for (int i = 0; i < DIM; i++) {
            Bf[r * ROWLEN + OFFE + tid * DIM + i] = aL[r][i] * s + bl;
            Cf[r * ROWLEN + OFFE + tid * DIM + i] = aR[r][i] * s + brr;
        }
}

template <int LI, int LJ, int LK, int OW>
__device__ __forceinline__ void tp_instr(const float* W3, const float* cl,
                                         const float* cr, float* o, float f) {
    constexpr int di = 2 * LI + 1, dj = 2 * LJ + 1, dk = 2 * LK + 1;
    constexpr int oi = (LI == 0) ? 0 : ((LI == 1) ? 1 : 4);
    constexpr int oj = (LJ == 0) ? 0 : ((LJ == 1) ? 1 : 4);
    constexpr int ok = (LK == 0) ? 0 : ((LK == 1) ? 1 : 4);
    float tmp[dk];
#pragma unroll
    for (int z = 0; z < dk; z++) tmp[z] = 0.f;
#pragma unroll
    for (int xi = 0; xi < di; xi++)
#pragma unroll
        for (int yj = 0; yj < dj; yj++) {
            float p = cl[oi + xi] * cr[oj + yj];
#pragma unroll
            for (int z = 0; z < dk; z++)
                tmp[z] = fmaf(W3[OW + (xi * dj + yj) * dk + z], p, tmp[z]);
        }
#pragma unroll
    for (int z = 0; z < dk; z++) o[ok + z] = fmaf(f, tmp[z], o[ok + z]);
}

template <int DIM, int OFFE, int L>
__device__ __forceinline__ void lin_p(const float* __restrict__ W,
                                      const float* __restrict__ b,
                                      const float* A, float* Bf, float* RED, int tid) {
    float a[TR][DIM];
#pragma unroll
    for (int r = 0; r < TR; r++)
#pragma unroll
        for (int i = 0; i < DIM; i++) a[r][i] = 0.f;
#pragma unroll 2
    for (int u = 0; u < 128; u++) {
        float w = __ldg(W + u * 128 + tid);
#pragma unroll
        for (int r = 0; r < TR; r++)
#pragma unroll
            for (int i = 0; i < DIM; i++)
                a[r][i] = fmaf(A[r * ROWLEN + OFFE + u * DIM + i], w, a[r][i]);
    }
    const float s = 0.08838834764831845f;
    float bb = (L == 0) ? b[tid] : 0.f;
#pragma unroll
    for (int r = 0; r < TR; r++) {
        float s2 = 0.f, s1 = 0.f;
#pragma unroll
        for (int i = 0; i < DIM; i++) {
            float c = a[r][i] * s + bb;
            Bf[r * ROWLEN + OFFE + tid * DIM + i] = c;
            s2 = fmaf(c, c, s2);
            s1 += c;
        }
#pragma unroll
        for (int off = 16; off; off >>= 1) {
            s2 += __shfl_xor_sync(0xffffffffu, s2, off);
            if (L == 0) s1 += __shfl_xor_sync(0xffffffffu, s1, off);
        }
        if ((tid & 31) == 0) {
            RED[(r * 3 + L) * 4 + (tid >> 5)] = s2;
            if (L == 0) RED[48 + r * 4 + (tid >> 5)] = s1;
        }
    }
}

__global__ __launch_bounds__(NT) void self_layer_kernel(
    const float* __restrict__ x, const float* __restrict__ oldf,
    const float* __restrict__ lw, const float* __restrict__ lb,
    const float* __restrict__ rw, const float* __restrict__ rb,
    const float* __restrict__ pwm, const float* __restrict__ pb,
    const float* __restrict__ tpw, const float* __restrict__ lnw,
    const float* __restrict__ lnb, float* __restrict__ out, int nrows) {
    extern __shared__ float sm[];
    float* A   = sm;                 // [4][1152]  x, then xtp
    float* Bf  = A + TR * ROWLEN;    // [4][1152]  xl, then fii
    float* Cf  = Bf + TR * ROWLEN;   // [4][1152]  xr
    float* W3  = Cf + TR * ROWLEN;   // 363 (padded 368)
    float* RED = W3 + 368;           // 48 (s2) + 16 (s1)

    const int tid = threadIdx.x;
    const int rowbase = blockIdx.x * TR;

    for (int i = tid; i < 363; i += NT) W3[i] = g_w3j[i];

    if (rowbase + TR <= nrows) {
        const float4* xv = reinterpret_cast<const float4*>(x + (size_t)rowbase * ROWLEN);
        float4* Av = reinterpret_cast<float4*>(A);
#pragma unroll
        for (int q = 0; q < 9; q++) Av[q * NT + tid] = xv[q * NT + tid];
    } else {
        for (int r = 0; r < TR; r++) {
            int row = rowbase + r;
            for (int i = tid; i < ROWLEN; i += NT)
                A[r * ROWLEN + i] = (row < nrows) ? x[(size_t)row * ROWLEN + i] : 0.f;
        }
    }
    __syncthreads();

    // --- linear L and R ---
    lin_lr<1, 0>(lw, rw, lb, rb, A, Bf, Cf, tid);
    lin_lr<3, 128>(lw + 16384, rw + 16384, lb, rb, A, Bf, Cf, tid);
    lin_lr<5, 512>(lw + 32768, rw + 32768, lb, rb, A, Bf, Cf, tid);
    __syncthreads();

    // --- tensor product ('uuu'), u = tid ---
    {
        float tw[11];
#pragma unroll
        for (int n = 0; n < 11; n++) tw[n] = __ldg(tpw + n * 128 + tid);
        const float PW0 = 0.5773502691896258f;   // sqrt(1/3)
        const float PW1 = 0.8660254037844386f;   // sqrt(3/4)
        const float PW2 = 1.1180339887498949f;   // sqrt(5/4)
#pragma unroll
        for (int r = 0; r < TR; r++) {
            const float* bl_ = Bf + r * ROWLEN;
            const float* cr_ = Cf + r * ROWLEN;
            float cl[9], cr[9];
            cl[0] = bl_[tid]; cr[0] = cr_[tid];
#pragma unroll
            for (int i = 0; i < 3; i++) { cl[1 + i] = bl_[128 + tid * 3 + i]; cr[1 + i] = cr_[128 + tid * 3 + i]; }
#pragma unroll
            for (int i = 0; i < 5; i++) { cl[4 + i] = bl_[512 + tid * 5 + i]; cr[4 + i] = cr_[512 + tid * 5 + i]; }
            float o[9];
#pragma unroll
            for (int i = 0; i < 9; i++) o[i] = 0.f;
            tp_instr<0, 0, 0, 0>(W3, cl, cr, o, PW0 * tw[0]);
            tp_instr<0, 1, 1, 1>(W3, cl, cr, o, PW1 * tw[1]);
            tp_instr<0, 2, 2, 10>(W3, cl, cr, o, PW2 * tw[2]);
            tp_instr<1, 0, 1, 35>(W3, cl, cr, o, PW1 * tw[3]);
            tp_instr<1, 1, 0, 44>(W3, cl, cr, o, PW0 * tw[4]);
            tp_instr<1, 1, 2, 53>(W3, cl, cr, o, PW2 * tw[5]);
            tp_instr<1, 2, 1, 98>(W3, cl, cr, o, PW1 * tw[6]);
            tp_instr<2, 0, 2, 143>(W3, cl, cr, o, PW2 * tw[7]);
            tp_instr<2, 1, 1, 168>(W3, cl, cr, o, PW1 * tw[8]);
            tp_instr<2, 2, 0, 213>(W3, cl, cr, o, PW0 * tw[9]);
            tp_instr<2, 2, 2, 238>(W3, cl, cr, o, PW2 * tw[10]);
            float* ar_ = A + r * ROWLEN;  // overwrite x with xtp
            ar_[tid] = o[0];
#pragma unroll
            for (int i = 0; i < 3; i++) ar_[128 + tid * 3 + i] = o[1 + i];
#pragma unroll
            for (int i = 0; i < 5; i++) ar_[512 + tid * 5 + i] = o[4 + i];
        }
    }
    __syncthreads();

    // --- linear P (fii into Bf) + per-(row,l) stats ---
    lin_p<1, 0, 0>(pwm, pb, A, Bf, RED, tid);
    lin_p<3, 128, 1>(pwm + 16384, pb, A, Bf, RED, tid);
    lin_p<5, 512, 2>(pwm + 32768, pb, A, Bf, RED, tid);
    __syncthreads();

    // --- e3norm stats ---
    float inv0[TR], inv1[TR], inv2[TR], mu[TR];
#pragma unroll
    for (int r = 0; r < TR; r++) {
        float s1 = RED[48 + r * 4 + 0] + RED[48 + r * 4 + 1] + RED[48 + r * 4 + 2] + RED[48 + r * 4 + 3];
        mu[r] = s1 * (1.f / 128.f);
        float q0 = RED[(r * 3 + 0) * 4 + 0] + RED[(r * 3 + 0) * 4 + 1] + RED[(r * 3 + 0) * 4 + 2] + RED[(r * 3 + 0) * 4 + 3];
        float q1 = RED[(r * 3 + 1) * 4 + 0] + RED[(r * 3 + 1) * 4 + 1] + RED[(r * 3 + 1) * 4 + 2] + RED[(r * 3 + 1) * 4 + 3];
        float q2 = RED[(r * 3 + 2) * 4 + 0] + RED[(r * 3 + 2) * 4 + 1] + RED[(r * 3 + 2) * 4 + 2] + RED[(r * 3 + 2) * 4 + 3];
        float fn0 = q0 * (1.f / 128.f) - mu[r] * mu[r];  // centered variance
        inv0[r] = rsqrtf(fn0 + 1e-5f);
        inv1[r] = rsqrtf(q1 * (1.f / 384.f) + 1e-5f);
        inv2[r] = rsqrtf(q2 * (1.f / 640.f) + 1e-5f);
    }

    // --- normalize + residual + store ---
#pragma unroll
    for (int r = 0; r < TR; r++) {
        int row = rowbase + r;
        if (row >= nrows) continue;
        const float* frow = Bf + r * ROWLEN;
        size_t gbase = (size_t)row * ROWLEN;
#pragma unroll
        for (int q = 0; q < 9; q++) {
            int e = q * NT + tid;
            float c = frow[e];
            float v;
            if (e < 128) {
                v = (c - mu[r]) * inv0[r] * __ldg(lnw + e) + __ldg(lnb + e);
            } else if (e < 512) {
                int u = (e - 128) / 3;
                v = c * inv1[r] * __ldg(lnw + 128 + u);
            } else {
                int u = (e - 512) / 5;
                v = c * inv2[r] * __ldg(lnw + 256 + u);
            }
            out[gbase + e] = v + __ldg(oldf + gbase + e);
        }
    }
}

// ---------------------------------------------------------------------------
extern "C" void kernel_launch(void* const* d_in, const int* in_sizes, int n_in,
                              void* d_out, int out_size) {
    const float* x    = (const float*)d_in[0];
    const float* oldf = (const float*)d_in[1];
    const float* lw   = (const float*)d_in[2];
    const float* lb   = (const float*)d_in[3];
    const float* rw   = (const float*)d_in[4];
    const float* rb   = (const float*)d_in[5];
    const float* pwm  = (const float*)d_in[6];
    const float* pb   = (const float*)d_in[7];
    const float* tpw  = (const float*)d_in[8];
    const float* lnw  = (const float*)d_in[9];
    const float* lnb  = (const float*)d_in[10];
    float* out = (float*)d_out;

    int nrows = in_sizes[0] / ROWLEN;
    const int smem_bytes = (TR * ROWLEN * 3 + 368 + 64) * sizeof(float);  // 57024

    cudaFuncSetAttribute(self_layer_kernel,
                         cudaFuncAttributeMaxDynamicSharedMemorySize, smem_bytes);

    w3j_init_kernel<<<1, 32>>>();

    int grid = (nrows + TR - 1) / TR;
    self_layer_kernel<<<grid, NT, smem_bytes>>>(x, oldf, lw, lb, rw, rb, pwm, pb,
                                                tpw, lnw, lnb, out, nrows);
}

// round 7
// speedup vs baseline: 4.8095x; 4.8095x over previous
#include <cuda_runtime.h>
#include <math.h>

#define ROWLEN 1152
#define TR 4
#define NT 128

// ---------------------------------------------------------------------------
// Wigner-3j (real basis, e3nn phase convention) computed on device at launch.
// Layout: per-instruction dense [di,dj,dk], offsets below. Total 363 floats.
// ---------------------------------------------------------------------------
__device__ float g_w3j[363];

__device__ __forceinline__ double dfact(int n) {
    double r = 1.0;
    for (int i = 2; i <= n; i++) r *= (double)i;
    return r;
}

__device__ double cg_racah(int j1, int m1, int j2, int m2, int j3, int m3) {
    if (m1 + m2 != m3) return 0.0;
    double pre = sqrt((2.0 * j3 + 1.0) * dfact(j3 + j1 - j2) * dfact(j3 - j1 + j2) *
                      dfact(j1 + j2 - j3) / dfact(j1 + j2 + j3 + 1));
    pre *= sqrt(dfact(j3 + m3) * dfact(j3 - m3) * dfact(j1 - m1) * dfact(j1 + m1) *
                dfact(j2 - m2) * dfact(j2 + m2));
    double s = 0.0;
    for (int k = 0; k <= j1 + j2 - j3; k++) {
        int d0 = k, d1 = j1 + j2 - j3 - k, d2 = j1 - m1 - k, d3 = j2 + m2 - k;
        int d4 = j3 - j2 + m1 + k, d5 = j3 - j1 - m2 + k;
        if (d0 < 0 || d1 < 0 || d2 < 0 || d3 < 0 || d4 < 0 || d5 < 0) continue;
        s += ((k & 1) ? -1.0 : 1.0) /
             (dfact(d0) * dfact(d1) * dfact(d2) * dfact(d3) * dfact(d4) * dfact(d5));
    }
    return pre * s;
}

// Row x of the complex->real change-of-basis Q(l). Returns #nonzero cols (<=2).
__device__ int qrow(int l, int x, int* col, double* qre, double* qim) {
    const double s = 0.70710678118654752440;
    if (x == l) { col[0] = l; qre[0] = 1.0; qim[0] = 0.0; return 1; }
    if (x > l) {
        int m = x - l;
        col[0] = l - m; qre[0] = s;                 qim[0] = 0.0;
        col[1] = l + m; qre[1] = (m & 1) ? -s : s;  qim[1] = 0.0;
        return 2;
    }
    int m = l - x;
    col[0] = l - m; qre[0] = 0.0; qim[0] = s;
    col[1] = l + m; qre[1] = 0.0; qim[1] = (m & 1) ? s : -s;  // -i*(-1)^m/sqrt2
    return 2;
}

__global__ void w3j_init_kernel() {
    __shared__ double WS[11][384];
    int t = threadIdx.x;
    if (t >= 11) return;
    const int L1[11] = {0,0,0,1,1,1,1,2,2,2,2};
    const int L2[11] = {0,1,2,0,1,1,2,0,1,2,2};
    const int L3[11] = {0,1,2,1,0,2,1,2,1,0,2};
    const int OFF[11] = {0,1,10,35,44,53,98,143,168,213,238};
    int l1 = L1[t], l2 = L2[t], l3 = L3[t];
    int d1 = 2*l1+1, d2 = 2*l2+1, d3 = 2*l3+1;
    double* Wc  = WS[t];
    double* Wre = Wc + 125;
    double* Wim = Wre + 125;
    for (int i = 0; i < 125; i++) Wc[i] = 0.0;

    // complex w3j (purely real values)
    for (int m1 = -l1; m1 <= l1; m1++)
        for (int m2 = -l2; m2 <= l2; m2++) {
            int m3 = -(m1 + m2);
            if (m3 < -l3 || m3 > l3) continue;
            int e = l1 - l2 - m3;
            double par = (((e % 2) + 2) % 2) ? -1.0 : 1.0;
            Wc[((m1 + l1) * d2 + (m2 + l2)) * d3 + (m3 + l3)] =
                par / sqrt(2.0 * l3 + 1.0) * cg_racah(l1, m1, l2, m2, l3, -m3);
        }

    // real basis: W[x,y,z] = sum_{a,b,c} Q1[x,a] Q2[y,b] Q3[z,c] Wc[a,b,c]
    for (int x = 0; x < d1; x++) {
        int ca[2]; double ar[2], ai[2]; int na = qrow(l1, x, ca, ar, ai);
        for (int y = 0; y < d2; y++) {
            int cb[2]; double br[2], bi[2]; int nb = qrow(l2, y, cb, br, bi);
            for (int z = 0; z < d3; z++) {
                int cc[2]; double cr[2], ci[2]; int nc = qrow(l3, z, cc, cr, ci);
                double sr = 0.0, si = 0.0;
                for (int ia = 0; ia < na; ia++)
                    for (int ib = 0; ib < nb; ib++) {
                        double pre = ar[ia]*br[ib] - ai[ia]*bi[ib];
                        double pim = ar[ia]*bi[ib] + ai[ia]*br[ib];
                        for (int ic = 0; ic < nc; ic++) {
                            double wc = Wc[(ca[ia]*d2 + cb[ib])*d3 + cc[ic]];
                            if (wc == 0.0) continue;
                            double qre = pre*cr[ic] - pim*ci[ic];
                            double qim = pre*ci[ic] + pim*cr[ic];
                            sr += qre * wc;
                            si += qim * wc;
                        }
                    }
                Wre[(x*d2 + y)*d3 + z] = sr;
                Wim[(x*d2 + y)*d3 + z] = si;
            }
        }
    }

    // Phase normalization: divide by phase of the max-abs element.
    // (2,2,2) has sign-mixed ties at max magnitude; numpy's argmax lands on the
    // d0*d0*d0 diagonal (flat 62) -> pin there. Others are unambiguous.
    int n = d1 * d2 * d3;
    int idx;
    if (l1 == 2 && l2 == 2 && l3 == 2) {
        idx = (2 * d2 + 2) * d3 + 2;  // flat 62
    } else {
        double M = 0.0;
        for (int i = 0; i < n; i++) {
            double h = sqrt(Wre[i]*Wre[i] + Wim[i]*Wim[i]);
            if (h > M) M = h;
        }
        idx = 0;
        for (int i = 0; i < n; i++) {
            double h = sqrt(Wre[i]*Wre[i] + Wim[i]*Wim[i]);
            if (h >= M * (1.0 - 1e-9)) { idx = i; break; }
        }
    }
    double h = sqrt(Wre[idx]*Wre[idx] + Wim[idx]*Wim[idx]);
    double pr = Wre[idx] / h, pi = Wim[idx] / h;
    for (int i = 0; i < n; i++)
        g_w3j[OFF[t] + i] = (float)(Wre[i]*pr + Wim[i]*pi);  // W * conj(phase), real part
}

// ---------------------------------------------------------------------------
// Fused main kernel: linL/linR -> TP -> linP -> e3norm -> +old_fii
// One CTA = 128 threads, TR=4 rows. All intermediates in smem.
// __launch_bounds__(128, 4): smem caps occupancy at 4 CTAs/SM anyway, so allow
// up to 128 regs/thread -> accumulators stay in registers (no spills).
// ---------------------------------------------------------------------------

template <int DIM, int OFFE>
__device__ __forceinline__ void lin_lr(const float* __restrict__ WL,
                                       const float* __restrict__ WR,
                                       const float* __restrict__ bL,
                                       const float* __restrict__ bR,
                                       const float* A, float* Bf, float* Cf, int tid) {
    float aL[TR][DIM], aR[TR][DIM];
#pragma unroll
    for (int r = 0; r < TR; r++)
#pragma unroll
        for (int i = 0; i < DIM; i++) { aL[r][i] = 0.f; aR[r][i] = 0.f; }
#pragma unroll 4
    for (int u = 0; u < 128; u++) {
        float wl = __ldg(WL + u * 128 + tid);
        float wr = __ldg(WR + u * 128 + tid);
#pragma unroll
        for (int r = 0; r < TR; r++)
#pragma unroll
            for (int i = 0; i < DIM; i++) {
                float xv = A[r * ROWLEN + OFFE + u * DIM + i];
                aL[r][i] = fmaf(xv, wl, aL[r][i]);
                aR[r][i] = fmaf(xv, wr, aR[r][i]);
            }
    }
    const float s = 0.08838834764831845f;  // 1/sqrt(128)
    float bl = (DIM == 1) ? bL[tid] : 0.f;
    float brr = (DIM == 1) ? bR[tid] : 0.f;
#pragma unroll
    for (int r = 0; r < TR; r++)
#pragma unroll
        for (int i = 0; i < DIM; i++) {
            Bf[r * ROWLEN + OFFE + tid * DIM + i] = aL[r][i] * s + bl;
            Cf[r * ROWLEN + OFFE + tid * DIM + i] = aR[r][i] * s + brr;
        }
}

template <int LI, int LJ, int LK, int OW>
__device__ __forceinline__ void tp_instr(const float* W3, const float* cl,
                                         const float* cr, float* o, float f) {
    constexpr int di = 2 * LI + 1, dj = 2 * LJ + 1, dk = 2 * LK + 1;
    constexpr int oi = (LI == 0) ? 0 : ((LI == 1) ? 1 : 4);
    constexpr int oj = (LJ == 0) ? 0 : ((LJ == 1) ? 1 : 4);
    constexpr int ok = (LK == 0) ? 0 : ((LK == 1) ? 1 : 4);
    float tmp[dk];
#pragma unroll
    for (int z = 0; z < dk; z++) tmp[z] = 0.f;
#pragma unroll
    for (int xi = 0; xi < di; xi++)
#pragma unroll
        for (int yj = 0; yj < dj; yj++) {
            float p = cl[oi + xi] * cr[oj + yj];
#pragma unroll
            for (int z = 0; z < dk; z++)
                tmp[z] = fmaf(W3[OW + (xi * dj + yj) * dk + z], p, tmp[z]);
        }
#pragma unroll
    for (int z = 0; z < dk; z++) o[ok + z] = fmaf(f, tmp[z], o[ok + z]);
}

template <int DIM, int OFFE, int L>
__device__ __forceinline__ void lin_p(const float* __restrict__ W,
                                      const float* __restrict__ b,
                                      const float* A, float* Bf, float* RED, int tid) {
    float a[TR][DIM];
#pragma unroll
    for (int r = 0; r < TR; r++)
#pragma unroll
        for (int i = 0; i < DIM; i++) a[r][i] = 0.f;
#pragma unroll 4
    for (int u = 0; u < 128; u++) {
        float w = __ldg(W + u * 128 + tid);
#pragma unroll
        for (int r = 0; r < TR; r++)
#pragma unroll
            for (int i = 0; i < DIM; i++)
                a[r][i] = fmaf(A[r * ROWLEN + OFFE + u * DIM + i], w, a[r][i]);
    }
    const float s = 0.08838834764831845f;
    float bb = (L == 0) ? b[tid] : 0.f;
#pragma unroll
    for (int r = 0; r < TR; r++) {
        float s2 = 0.f, s1 = 0.f;
#pragma unroll
        for (int i = 0; i < DIM; i++) {
            float c = a[r][i] * s + bb;
            Bf[r * ROWLEN + OFFE + tid * DIM + i] = c;
            s2 = fmaf(c, c, s2);
            s1 += c;
        }
#pragma unroll
        for (int off = 16; off; off >>= 1) {
            s2 += __shfl_xor_sync(0xffffffffu, s2, off);
            if (L == 0) s1 += __shfl_xor_sync(0xffffffffu, s1, off);
        }
        if ((tid & 31) == 0) {
            RED[(r * 3 + L) * 4 + (tid >> 5)] = s2;
            if (L == 0) RED[48 + r * 4 + (tid >> 5)] = s1;
        }
    }
}

__global__ __launch_bounds__(NT, 4) void self_layer_kernel(
    const float* __restrict__ x, const float* __restrict__ oldf,
    const float* __restrict__ lw, const float* __restrict__ lb,
    const float* __restrict__ rw, const float* __restrict__ rb,
    const float* __restrict__ pwm, const float* __restrict__ pb,
    const float* __restrict__ tpw, const float* __restrict__ lnw,
    const float* __restrict__ lnb, float* __restrict__ out, int nrows) {
    extern __shared__ float sm[];
    float* A   = sm;                 // [4][1152]  x, then xtp
    float* Bf  = A + TR * ROWLEN;    // [4][1152]  xl, then fii
    float* Cf  = Bf + TR * ROWLEN;   // [4][1152]  xr
    float* W3  = Cf + TR * ROWLEN;   // 363 (padded 368)
    float* RED = W3 + 368;           // 48 (s2) + 16 (s1)

    const int tid = threadIdx.x;
    const int rowbase = blockIdx.x * TR;

    for (int i = tid; i < 363; i += NT) W3[i] = g_w3j[i];

    if (rowbase + TR <= nrows) {
        const float4* xv = reinterpret_cast<const float4*>(x + (size_t)rowbase * ROWLEN);
        float4* Av = reinterpret_cast<float4*>(A);
#pragma unroll
        for (int q = 0; q < 9; q++) Av[q * NT + tid] = xv[q * NT + tid];
    } else {
        for (int r = 0; r < TR; r++) {
            int row = rowbase + r;
            for (int i = tid; i < ROWLEN; i += NT)
                A[r * ROWLEN + i] = (row < nrows) ? x[(size_t)row * ROWLEN + i] : 0.f;
        }
    }
    __syncthreads();

    // --- linear L and R ---
    lin_lr<1, 0>(lw, rw, lb, rb, A, Bf, Cf, tid);
    lin_lr<3, 128>(lw + 16384, rw + 16384, lb, rb, A, Bf, Cf, tid);
    lin_lr<5, 512>(lw + 32768, rw + 32768, lb, rb, A, Bf, Cf, tid);
    __syncthreads();

    // --- tensor product ('uuu'), u = tid ---
    {
        float tw[11];
#pragma unroll
        for (int n = 0; n < 11; n++) tw[n] = __ldg(tpw + n * 128 + tid);
        const float PW0 = 0.5773502691896258f;   // sqrt(1/3)
        const float PW1 = 0.8660254037844386f;   // sqrt(3/4)
        const float PW2 = 1.1180339887498949f;   // sqrt(5/4)
#pragma unroll
        for (int r = 0; r < TR; r++) {
            const float* bl_ = Bf + r * ROWLEN;
            const float* cr_ = Cf + r * ROWLEN;
            float cl[9], cr[9];
            cl[0] = bl_[tid]; cr[0] = cr_[tid];
#pragma unroll
            for (int i = 0; i < 3; i++) { cl[1 + i] = bl_[128 + tid * 3 + i]; cr[1 + i] = cr_[128 + tid * 3 + i]; }
#pragma unroll
            for (int i = 0; i < 5; i++) { cl[4 + i] = bl_[512 + tid * 5 + i]; cr[4 + i] = cr_[512 + tid * 5 + i]; }
            float o[9];
#pragma unroll
            for (int i = 0; i < 9; i++) o[i] = 0.f;
            tp_instr<0, 0, 0, 0>(W3, cl, cr, o, PW0 * tw[0]);
            tp_instr<0, 1, 1, 1>(W3, cl, cr, o, PW1 * tw[1]);
            tp_instr<0, 2, 2, 10>(W3, cl, cr, o, PW2 * tw[2]);
            tp_instr<1, 0, 1, 35>(W3, cl, cr, o, PW1 * tw[3]);
            tp_instr<1, 1, 0, 44>(W3, cl, cr, o, PW0 * tw[4]);
            tp_instr<1, 1, 2, 53>(W3, cl, cr, o, PW2 * tw[5]);
            tp_instr<1, 2, 1, 98>(W3, cl, cr, o, PW1 * tw[6]);
            tp_instr<2, 0, 2, 143>(W3, cl, cr, o, PW2 * tw[7]);
            tp_instr<2, 1, 1, 168>(W3, cl, cr, o, PW1 * tw[8]);
            tp_instr<2, 2, 0, 213>(W3, cl, cr, o, PW0 * tw[9]);
            tp_instr<2, 2, 2, 238>(W3, cl, cr, o, PW2 * tw[10]);
            float* ar_ = A + r * ROWLEN;  // overwrite x with xtp
            ar_[tid] = o[0];
#pragma unroll
            for (int i = 0; i < 3; i++) ar_[128 + tid * 3 + i] = o[1 + i];
#pragma unroll
            for (int i = 0; i < 5; i++) ar_[512 + tid * 5 + i] = o[4 + i];
        }
    }
    __syncthreads();

    // --- linear P (fii into Bf) + per-(row,l) stats ---
    lin_p<1, 0, 0>(pwm, pb, A, Bf, RED, tid);
    lin_p<3, 128, 1>(pwm + 16384, pb, A, Bf, RED, tid);
    lin_p<5, 512, 2>(pwm + 32768, pb, A, Bf, RED, tid);
    __syncthreads();

    // --- e3norm stats ---
    float inv0[TR], inv1[TR], inv2[TR], mu[TR];
#pragma unroll
    for (int r = 0; r < TR; r++) {
        float s1 = RED[48 + r * 4 + 0] + RED[48 + r * 4 + 1] + RED[48 + r * 4 + 2] + RED[48 + r * 4 + 3];
        mu[r] = s1 * (1.f / 128.f);
        float q0 = RED[(r * 3 + 0) * 4 + 0] + RED[(r * 3 + 0) * 4 + 1] + RED[(r * 3 + 0) * 4 + 2] + RED[(r * 3 + 0) * 4 + 3];
        float q1 = RED[(r * 3 + 1) * 4 + 0] + RED[(r * 3 + 1) * 4 + 1] + RED[(r * 3 + 1) * 4 + 2] + RED[(r * 3 + 1) * 4 + 3];
        float q2 = RED[(r * 3 + 2) * 4 + 0] + RED[(r * 3 + 2) * 4 + 1] + RED[(r * 3 + 2) * 4 + 2] + RED[(r * 3 + 2) * 4 + 3];
        float fn0 = q0 * (1.f / 128.f) - mu[r] * mu[r];  // centered variance
        inv0[r] = rsqrtf(fn0 + 1e-5f);
        inv1[r] = rsqrtf(q1 * (1.f / 384.f) + 1e-5f);
        inv2[r] = rsqrtf(q2 * (1.f / 640.f) + 1e-5f);
    }

    // --- normalize + residual + store ---
#pragma unroll
    for (int r = 0; r < TR; r++) {
        int row = rowbase + r;
        if (row >= nrows) continue;
        const float* frow = Bf + r * ROWLEN;
        size_t gbase = (size_t)row * ROWLEN;
#pragma unroll
        for (int q = 0; q < 9; q++) {
            int e = q * NT + tid;
            float c = frow[e];
            float v;
            if (e < 128) {
                v = (c - mu[r]) * inv0[r] * __ldg(lnw + e) + __ldg(lnb + e);
            } else if (e < 512) {
                int u = (e - 128) / 3;
                v = c * inv1[r] * __ldg(lnw + 128 + u);
            } else {
                int u = (e - 512) / 5;
                v = c * inv2[r] * __ldg(lnw + 256 + u);
            }
            out[gbase + e] = v + __ldg(oldf + gbase + e);
        }
    }
}

// ---------------------------------------------------------------------------
extern "C" void kernel_launch(void* const* d_in, const int* in_sizes, int n_in,
                              void* d_out, int out_size) {
    const float* x    = (const float*)d_in[0];
    const float* oldf = (const float*)d_in[1];
    const float* lw   = (const float*)d_in[2];
    const float* lb   = (const float*)d_in[3];
    const float* rw   = (const float*)d_in[4];
    const float* rb   = (const float*)d_in[5];
    const float* pwm  = (const float*)d_in[6];
    const float* pb   = (const float*)d_in[7];
    const float* tpw  = (const float*)d_in[8];
    const float* lnw  = (const float*)d_in[9];
    const float* lnb  = (const float*)d_in[10];
    float* out = (float*)d_out;

    int nrows = in_sizes[0] / ROWLEN;
    const int smem_bytes = (TR * ROWLEN * 3 + 368 + 64) * sizeof(float);  // 57024

    cudaFuncSetAttribute(self_layer_kernel,
                         cudaFuncAttributeMaxDynamicSharedMemorySize, smem_bytes);

    w3j_init_kernel<<<1, 32>>>();

    int grid = (nrows + TR - 1) / TR;
    self_layer_kernel<<<grid, NT, smem_bytes>>>(x, oldf, lw, lb, rw, rb, pwm, pb,
                                                tpw, lnw, lnb, out, nrows);
}

// round 8
// speedup vs baseline: 6.3462x; 1.3195x over previous
#include <cuda_runtime.h>
#include <math.h>

#define ROWLEN 1152
#define PROW   1408   // padded smem row: l0 [0,128), l1 @128 stride4, l2 @640 stride6
#define TR     4
#define NT     128

// ---------------------------------------------------------------------------
// Wigner-3j (real basis, e3nn phase convention) computed on device at launch.
// ---------------------------------------------------------------------------
__device__ float g_w3j[363];

__device__ __forceinline__ double dfact(int n) {
    double r = 1.0;
    for (int i = 2; i <= n; i++) r *= (double)i;
    return r;
}

__device__ double cg_racah(int j1, int m1, int j2, int m2, int j3, int m3) {
    if (m1 + m2 != m3) return 0.0;
    double pre = sqrt((2.0 * j3 + 1.0) * dfact(j3 + j1 - j2) * dfact(j3 - j1 + j2) *
                      dfact(j1 + j2 - j3) / dfact(j1 + j2 + j3 + 1));
    pre *= sqrt(dfact(j3 + m3) * dfact(j3 - m3) * dfact(j1 - m1) * dfact(j1 + m1) *
                dfact(j2 - m2) * dfact(j2 + m2));
    double s = 0.0;
    for (int k = 0; k <= j1 + j2 - j3; k++) {
        int d0 = k, d1 = j1 + j2 - j3 - k, d2 = j1 - m1 - k, d3 = j2 + m2 - k;
        int d4 = j3 - j2 + m1 + k, d5 = j3 - j1 - m2 + k;
        if (d0 < 0 || d1 < 0 || d2 < 0 || d3 < 0 || d4 < 0 || d5 < 0) continue;
        s += ((k & 1) ? -1.0 : 1.0) /
             (dfact(d0) * dfact(d1) * dfact(d2) * dfact(d3) * dfact(d4) * dfact(d5));
    }
    return pre * s;
}

__device__ int qrow(int l, int x, int* col, double* qre, double* qim) {
    const double s = 0.70710678118654752440;
    if (x == l) { col[0] = l; qre[0] = 1.0; qim[0] = 0.0; return 1; }
    if (x > l) {
        int m = x - l;
        col[0] = l - m; qre[0] = s;                 qim[0] = 0.0;
        col[1] = l + m; qre[1] = (m & 1) ? -s : s;  qim[1] = 0.0;
        return 2;
    }
    int m = l - x;
    col[0] = l - m; qre[0] = 0.0; qim[0] = s;
    col[1] = l + m; qre[1] = 0.0; qim[1] = (m & 1) ? s : -s;
    return 2;
}

__global__ void w3j_init_kernel() {
    __shared__ double WS[11][384];
    int t = threadIdx.x;
    if (t >= 11) return;
    const int L1[11] = {0,0,0,1,1,1,1,2,2,2,2};
    const int L2[11] = {0,1,2,0,1,1,2,0,1,2,2};
    const int L3[11] = {0,1,2,1,0,2,1,2,1,0,2};
    const int OFF[11] = {0,1,10,35,44,53,98,143,168,213,238};
    int l1 = L1[t], l2 = L2[t], l3 = L3[t];
    int d1 = 2*l1+1, d2 = 2*l2+1, d3 = 2*l3+1;
    double* Wc  = WS[t];
    double* Wre = Wc + 125;
    double* Wim = Wre + 125;
    for (int i = 0; i < 125; i++) Wc[i] = 0.0;

    for (int m1 = -l1; m1 <= l1; m1++)
        for (int m2 = -l2; m2 <= l2; m2++) {
            int m3 = -(m1 + m2);
            if (m3 < -l3 || m3 > l3) continue;
            int e = l1 - l2 - m3;
            double par = (((e % 2) + 2) % 2) ? -1.0 : 1.0;
            Wc[((m1 + l1) * d2 + (m2 + l2)) * d3 + (m3 + l3)] =
                par / sqrt(2.0 * l3 + 1.0) * cg_racah(l1, m1, l2, m2, l3, -m3);
        }

    for (int x = 0; x < d1; x++) {
        int ca[2]; double ar[2], ai[2]; int na = qrow(l1, x, ca, ar, ai);
        for (int y = 0; y < d2; y++) {
            int cb[2]; double br[2], bi[2]; int nb = qrow(l2, y, cb, br, bi);
            for (int z = 0; z < d3; z++) {
                int cc[2]; double cr[2], ci[2]; int nc = qrow(l3, z, cc, cr, ci);
                double sr = 0.0, si = 0.0;
                for (int ia = 0; ia < na; ia++)
                    for (int ib = 0; ib < nb; ib++) {
                        double pre = ar[ia]*br[ib] - ai[ia]*bi[ib];
                        double pim = ar[ia]*bi[ib] + ai[ia]*br[ib];
                        for (int ic = 0; ic < nc; ic++) {
                            double wc = Wc[(ca[ia]*d2 + cb[ib])*d3 + cc[ic]];
                            if (wc == 0.0) continue;
                            double qre = pre*cr[ic] - pim*ci[ic];
                            double qim = pre*ci[ic] + pim*cr[ic];
                            sr += qre * wc;
                            si += qim * wc;
                        }
                    }
                Wre[(x*d2 + y)*d3 + z] = sr;
                Wim[(x*d2 + y)*d3 + z] = si;
            }
        }
    }

    // Phase normalization. (2,2,2): numpy argmax tie-break lands on d0^3 (flat 62).
    int n = d1 * d2 * d3;
    int idx;
    if (l1 == 2 && l2 == 2 && l3 == 2) {
        idx = (2 * d2 + 2) * d3 + 2;
    } else {
        double M = 0.0;
        for (int i = 0; i < n; i++) {
            double h = sqrt(Wre[i]*Wre[i] + Wim[i]*Wim[i]);
            if (h > M) M = h;
        }
        idx = 0;
        for (int i = 0; i < n; i++) {
            double h = sqrt(Wre[i]*Wre[i] + Wim[i]*Wim[i]);
            if (h >= M * (1.0 - 1e-9)) { idx = i; break; }
        }
    }
    double h = sqrt(Wre[idx]*Wre[idx] + Wim[idx]*Wim[idx]);
    double pr = Wre[idx] / h, pi = Wim[idx] / h;
    for (int i = 0; i < n; i++)
        g_w3j[OFF[t] + i] = (float)(Wre[i]*pr + Wim[i]*pi);
}

// ---------------------------------------------------------------------------
// f32x2 helpers
// ---------------------------------------------------------------------------
__device__ __forceinline__ unsigned long long pack2f(float lo, float hi) {
    unsigned long long r;
    asm("mov.b64 %0, {%1, %2};" : "=l"(r) : "f"(lo), "f"(hi));
    return r;
}
__device__ __forceinline__ void ffma2(unsigned long long& d, unsigned long long a,
                                      unsigned long long b) {
    asm("fma.rn.f32x2 %0, %1, %2, %0;" : "+l"(d) : "l"(a), "l"(b));
}
__device__ __forceinline__ float2 unpack2(unsigned long long p) {
    float2 r;
    asm("mov.b64 {%0, %1}, %2;" : "=f"(r.x), "=f"(r.y) : "l"(p));
    return r;
}
union U4 { float4 q; unsigned long long p[2]; float f[4]; };
union U2 { float2 q; unsigned long long p; float f[2]; };

// Dense TP contraction from compact smem tensor.
template <int DI, int DJ, int DK>
__device__ __forceinline__ void tp_dense(const float* W, const float* cl,
                                         const float* cr, float* o, float f) {
    float tmp[DK];
#pragma unroll
    for (int z = 0; z < DK; z++) tmp[z] = 0.f;
#pragma unroll
    for (int x = 0; x < DI; x++)
#pragma unroll
        for (int y = 0; y < DJ; y++) {
            float p = cl[x] * cr[y];
#pragma unroll
            for (int z = 0; z < DK; z++)
                tmp[z] = fmaf(W[(x * DJ + y) * DK + z], p, tmp[z]);
        }
#pragma unroll
    for (int z = 0; z < DK; z++) o[z] = fmaf(f, tmp[z], o[z]);
}

// ---------------------------------------------------------------------------
// Fused main kernel
// ---------------------------------------------------------------------------
__global__ __launch_bounds__(NT, 4) void self_layer_kernel(
    const float* __restrict__ x, const float* __restrict__ oldf,
    const float* __restrict__ lw, const float* __restrict__ lb,
    const float* __restrict__ rw, const float* __restrict__ rb,
    const float* __restrict__ pwm, const float* __restrict__ pb,
    const float* __restrict__ tpw, const float* __restrict__ lnw,
    const float* __restrict__ lnb, float* __restrict__ out, int nrows) {
    extern __shared__ float sm[];
    float* A   = sm;                  // [TR][PROW]  x (padded), later xtp (padded)
    float* CW  = A + TR * PROW;       // 260 compact dense w3j
    float* RED = CW + 264;            // 48 s2 + 16 s1

    const int tid = threadIdx.x;
    const int rowbase = blockIdx.x * TR;
    const float S = 0.08838834764831845f;   // 1/sqrt(128)
    const float C3 = 0.57735026918962576f;  // 1/sqrt(3)
    const float C5 = 0.44721359549995794f;  // 1/sqrt(5)
    const float PW0 = 0.5773502691896258f;  // sqrt(1/3)
    const float PW1 = 0.8660254037844386f;  // sqrt(3/4)
    const float PW2 = 1.1180339887498949f;  // sqrt(5/4)

    // compact dense w3j: (1,1,2)@53 len45 -> 0; (1,2,1)@98 len45 -> 45;
    //                    (2,1,1)@168 len45 -> 90; (2,2,2)@238 len125 -> 135
    for (int i = tid; i < 45; i += NT)  CW[i]       = g_w3j[53 + i];
    for (int i = tid; i < 45; i += NT)  CW[45 + i]  = g_w3j[98 + i];
    for (int i = tid; i < 45; i += NT)  CW[90 + i]  = g_w3j[168 + i];
    for (int i = tid; i < 125; i += NT) CW[135 + i] = g_w3j[238 + i];

    // load x -> padded smem
    for (int r = 0; r < TR; r++) {
        int row = rowbase + r;
        const float* xrow = x + (size_t)row * ROWLEN;
        bool ok = row < nrows;
        for (int e = tid; e < ROWLEN; e += NT) {
            float v = ok ? __ldg(xrow + e) : 0.f;
            int p;
            if (e < 128) p = e;
            else if (e < 512) { int t = e - 128; p = 128 + (t / 3) * 4 + (t % 3); }
            else              { int t = e - 512; p = 640 + (t / 5) * 6 + (t % 5); }
            A[r * PROW + p] = v;
        }
    }
    __syncthreads();

    float xl[TR][9], xr[TR][9];

    // ---- linear L/R, l=0 ----
    {
        float aL[TR] = {0, 0, 0, 0}, aR[TR] = {0, 0, 0, 0};
#pragma unroll 2
        for (int g = 0; g < 128; g += 4) {
            float wl[4], wr[4];
#pragma unroll
            for (int k = 0; k < 4; k++) {
                wl[k] = __ldg(lw + (g + k) * 128 + tid);
                wr[k] = __ldg(rw + (g + k) * 128 + tid);
            }
#pragma unroll
            for (int r = 0; r < TR; r++) {
                U4 xq; xq.q = *reinterpret_cast<const float4*>(&A[r * PROW + g]);
#pragma unroll
                for (int k = 0; k < 4; k++) {
                    aL[r] = fmaf(xq.f[k], wl[k], aL[r]);
                    aR[r] = fmaf(xq.f[k], wr[k], aR[r]);
                }
            }
        }
        float bl = __ldg(lb + tid), br = __ldg(rb + tid);
#pragma unroll
        for (int r = 0; r < TR; r++) {
            xl[r][0] = aL[r] * S + bl;
            xr[r][0] = aR[r] * S + br;
        }
    }

    // ---- linear L/R, l=1 (f32x2 on pair (i0,i1), scalar i2) ----
    {
        unsigned long long pL[TR] = {0,0,0,0}, pR[TR] = {0,0,0,0};
        float sL[TR] = {0,0,0,0}, sR[TR] = {0,0,0,0};
        const float* WL = lw + 16384;
        const float* WR = rw + 16384;
#pragma unroll 2
        for (int g = 0; g < 128; g += 4) {
            float wl[4], wr[4];
#pragma unroll
            for (int k = 0; k < 4; k++) {
                wl[k] = __ldg(WL + (g + k) * 128 + tid);
                wr[k] = __ldg(WR + (g + k) * 128 + tid);
            }
#pragma unroll
            for (int k = 0; k < 4; k++) {
                unsigned long long wl2 = pack2f(wl[k], wl[k]);
                unsigned long long wr2 = pack2f(wr[k], wr[k]);
#pragma unroll
                for (int r = 0; r < TR; r++) {
                    U4 xq; xq.q = *reinterpret_cast<const float4*>(
                        &A[r * PROW + 128 + (g + k) * 4]);
                    ffma2(pL[r], xq.p[0], wl2);
                    ffma2(pR[r], xq.p[0], wr2);
                    sL[r] = fmaf(xq.f[2], wl[k], sL[r]);
                    sR[r] = fmaf(xq.f[2], wr[k], sR[r]);
                }
            }
        }
#pragma unroll
        for (int r = 0; r < TR; r++) {
            float2 t = unpack2(pL[r]);
            xl[r][1] = t.x * S; xl[r][2] = t.y * S; xl[r][3] = sL[r] * S;
            t = unpack2(pR[r]);
            xr[r][1] = t.x * S; xr[r][2] = t.y * S; xr[r][3] = sR[r] * S;
        }
    }

    // ---- linear L/R, l=2 (f32x2 on pairs (0,1),(2,3), scalar 4) ----
    {
        unsigned long long pL0[TR] = {0,0,0,0}, pL1[TR] = {0,0,0,0};
        unsigned long long pR0[TR] = {0,0,0,0}, pR1[TR] = {0,0,0,0};
        float sL[TR] = {0,0,0,0}, sR[TR] = {0,0,0,0};
        const float* WL = lw + 32768;
        const float* WR = rw + 32768;
#pragma unroll 2
        for (int g = 0; g < 128; g += 4) {
            float wl[4], wr[4];
#pragma unroll
            for (int k = 0; k < 4; k++) {
                wl[k] = __ldg(WL + (g + k) * 128 + tid);
                wr[k] = __ldg(WR + (g + k) * 128 + tid);
            }
#pragma unroll
            for (int k = 0; k < 4; k++) {
                unsigned long long wl2 = pack2f(wl[k], wl[k]);
                unsigned long long wr2 = pack2f(wr[k], wr[k]);
#pragma unroll
                for (int r = 0; r < TR; r++) {
                    const float* base = &A[r * PROW + 640 + (g + k) * 6];
                    U2 a, b;
                    a.q = *reinterpret_cast<const float2*>(base);
                    b.q = *reinterpret_cast<const float2*>(base + 2);
                    float x4 = base[4];
                    ffma2(pL0[r], a.p, wl2);
                    ffma2(pL1[r], b.p, wl2);
                    ffma2(pR0[r], a.p, wr2);
                    ffma2(pR1[r], b.p, wr2);
                    sL[r] = fmaf(x4, wl[k], sL[r]);
                    sR[r] = fmaf(x4, wr[k], sR[r]);
                }
            }
        }
#pragma unroll
        for (int r = 0; r < TR; r++) {
            float2 t = unpack2(pL0[r]);
            xl[r][4] = t.x * S; xl[r][5] = t.y * S;
            t = unpack2(pL1[r]);
            xl[r][6] = t.x * S; xl[r][7] = t.y * S; xl[r][8] = sL[r] * S;
            t = unpack2(pR0[r]);
            xr[r][4] = t.x * S; xr[r][5] = t.y * S;
            t = unpack2(pR1[r]);
            xr[r][6] = t.x * S; xr[r][7] = t.y * S; xr[r][8] = sR[r] * S;
        }
    }

    // ---- tensor product (registers only) ----
    float o[TR][9];
    {
        float tw[11];
#pragma unroll
        for (int n = 0; n < 11; n++) tw[n] = __ldg(tpw + n * 128 + tid);
        float f00  = PW0 * tw[0];
        float f0d1 = PW0 * C3 * tw[4];
        float f0d2 = PW0 * C5 * tw[9];
        float f1a  = PW1 * C3 * tw[1];   // (0,1,1)
        float f1b  = PW1 * C3 * tw[3];   // (1,0,1)
        float f2a  = PW2 * C5 * tw[2];   // (0,2,2)
        float f2b  = PW2 * C5 * tw[7];   // (2,0,2)
        float f112 = PW2 * tw[5];
        float f121 = PW1 * tw[6];
        float f211 = PW1 * tw[8];
        float f222 = PW2 * tw[10];
#pragma unroll
        for (int r = 0; r < TR; r++) {
            const float* cl = xl[r];
            const float* cr = xr[r];
            float t0 = f00 * cl[0] * cr[0];
            float d1 = cl[1] * cr[1] + cl[2] * cr[2] + cl[3] * cr[3];
            t0 = fmaf(f0d1, d1, t0);
            float d2 = cl[4] * cr[4] + cl[5] * cr[5] + cl[6] * cr[6] +
                       cl[7] * cr[7] + cl[8] * cr[8];
            t0 = fmaf(f0d2, d2, t0);
            o[r][0] = t0;
#pragma unroll
            for (int z = 0; z < 3; z++)
                o[r][1 + z] = f1a * cl[0] * cr[1 + z] + f1b * cl[1 + z] * cr[0];
#pragma unroll
            for (int z = 0; z < 5; z++)
                o[r][4 + z] = f2a * cl[0] * cr[4 + z] + f2b * cl[4 + z] * cr[0];
            tp_dense<3, 3, 5>(CW + 0,   cl + 1, cr + 1, &o[r][4], f112);
            tp_dense<3, 5, 3>(CW + 45,  cl + 1, cr + 4, &o[r][1], f121);
            tp_dense<5, 3, 3>(CW + 90,  cl + 4, cr + 1, &o[r][1], f211);
            tp_dense<5, 5, 5>(CW + 135, cl + 4, cr + 4, &o[r][4], f222);
        }
    }

    __syncthreads();  // all lin_lr reads of A done before overwrite
#pragma unroll
    for (int r = 0; r < TR; r++) {
        A[r * PROW + tid] = o[r][0];
#pragma unroll
        for (int i = 0; i < 3; i++) A[r * PROW + 128 + tid * 4 + i] = o[r][1 + i];
#pragma unroll
        for (int i = 0; i < 5; i++) A[r * PROW + 640 + tid * 6 + i] = o[r][4 + i];
    }
    __syncthreads();

    // ---- linear P -> fii in registers ----
    float fii[TR][9];
    {
        // l=0
        float a0[TR] = {0, 0, 0, 0};
#pragma unroll 2
        for (int g = 0; g < 128; g += 4) {
            float w[4];
#pragma unroll
            for (int k = 0; k < 4; k++) w[k] = __ldg(pwm + (g + k) * 128 + tid);
#pragma unroll
            for (int r = 0; r < TR; r++) {
                U4 xq; xq.q = *reinterpret_cast<const float4*>(&A[r * PROW + g]);
#pragma unroll
                for (int k = 0; k < 4; k++) a0[r] = fmaf(xq.f[k], w[k], a0[r]);
            }
        }
        float bb = __ldg(pb + tid);
#pragma unroll
        for (int r = 0; r < TR; r++) fii[r][0] = a0[r] * S + bb;
    }
    {
        // l=1
        unsigned long long p1[TR] = {0,0,0,0};
        float s1[TR] = {0,0,0,0};
        const float* W = pwm + 16384;
#pragma unroll 2
        for (int g = 0; g < 128; g += 4) {
            float w[4];
#pragma unroll
            for (int k = 0; k < 4; k++) w[k] = __ldg(W + (g + k) * 128 + tid);
#pragma unroll
            for (int k = 0; k < 4; k++) {
                unsigned long long w2 = pack2f(w[k], w[k]);
#pragma unroll
                for (int r = 0; r < TR; r++) {
                    U4 xq; xq.q = *reinterpret_cast<const float4*>(
                        &A[r * PROW + 128 + (g + k) * 4]);
                    ffma2(p1[r], xq.p[0], w2);
                    s1[r] = fmaf(xq.f[2], w[k], s1[r]);
                }
            }
        }
#pragma unroll
        for (int r = 0; r < TR; r++) {
            float2 t = unpack2(p1[r]);
            fii[r][1] = t.x * S; fii[r][2] = t.y * S; fii[r][3] = s1[r] * S;
        }
    }
    {
        // l=2
        unsigned long long p0[TR] = {0,0,0,0}, p1v[TR] = {0,0,0,0};
        float s2[TR] = {0,0,0,0};
        const float* W = pwm + 32768;
#pragma unroll 2
        for (int g = 0; g < 128; g += 4) {
            float w[4];
#pragma unroll
            for (int k = 0; k < 4; k++) w[k] = __ldg(W + (g + k) * 128 + tid);
#pragma unroll
            for (int k = 0; k < 4; k++) {
                unsigned long long w2 = pack2f(w[k], w[k]);
#pragma unroll
                for (int r = 0; r < TR; r++) {
                    const float* base = &A[r * PROW + 640 + (g + k) * 6];
                    U2 a, b;
                    a.q = *reinterpret_cast<const float2*>(base);
                    b.q = *reinterpret_cast<const float2*>(base + 2);
                    float x4 = base[4];
                    ffma2(p0[r], a.p, w2);
                    ffma2(p1v[r], b.p, w2);
                    s2[r] = fmaf(x4, w[k], s2[r]);
                }
            }
        }
#pragma unroll
        for (int r = 0; r < TR; r++) {
            float2 t = unpack2(p0[r]);
            fii[r][4] = t.x * S; fii[r][5] = t.y * S;
            t = unpack2(p1v[r]);
            fii[r][6] = t.x * S; fii[r][7] = t.y * S; fii[r][8] = s2[r] * S;
        }
    }

    // ---- stats (shuffle + cross-warp via RED) ----
#pragma unroll
    for (int r = 0; r < TR; r++) {
        float c0 = fii[r][0];
        float q0 = c0 * c0;
        float s1 = c0;
        float q1 = fii[r][1] * fii[r][1] + fii[r][2] * fii[r][2] + fii[r][3] * fii[r][3];
        float q2 = fii[r][4] * fii[r][4] + fii[r][5] * fii[r][5] + fii[r][6] * fii[r][6] +
                   fii[r][7] * fii[r][7] + fii[r][8] * fii[r][8];
#pragma unroll
        for (int off = 16; off; off >>= 1) {
            q0 += __shfl_xor_sync(0xffffffffu, q0, off);
            s1 += __shfl_xor_sync(0xffffffffu, s1, off);
            q1 += __shfl_xor_sync(0xffffffffu, q1, off);
            q2 += __shfl_xor_sync(0xffffffffu, q2, off);
        }
        if ((tid & 31) == 0) {
            int w = tid >> 5;
            RED[(r * 3 + 0) * 4 + w] = q0;
            RED[(r * 3 + 1) * 4 + w] = q1;
            RED[(r * 3 + 2) * 4 + w] = q2;
            RED[48 + r * 4 + w] = s1;
        }
    }
    __syncthreads();

    float mu[TR], inv0[TR], inv1[TR], inv2[TR];
#pragma unroll
    for (int r = 0; r < TR; r++) {
        float s1 = RED[48 + r * 4 + 0] + RED[48 + r * 4 + 1] +
                   RED[48 + r * 4 + 2] + RED[48 + r * 4 + 3];
        mu[r] = s1 * (1.f / 128.f);
        float q0 = RED[(r * 3 + 0) * 4 + 0] + RED[(r * 3 + 0) * 4 + 1] +
                   RED[(r * 3 + 0) * 4 + 2] + RED[(r * 3 + 0) * 4 + 3];
        float q1 = RED[(r * 3 + 1) * 4 + 0] + RED[(r * 3 + 1) * 4 + 1] +
                   RED[(r * 3 + 1) * 4 + 2] + RED[(r * 3 + 1) * 4 + 3];
        float q2 = RED[(r * 3 + 2) * 4 + 0] + RED[(r * 3 + 2) * 4 + 1] +
                   RED[(r * 3 + 2) * 4 + 2] + RED[(r * 3 + 2) * 4 + 3];
        float fn0 = q0 * (1.f / 128.f) - mu[r] * mu[r];
        inv0[r] = rsqrtf(fn0 + 1e-5f);
        inv1[r] = rsqrtf(q1 * (1.f / 384.f) + 1e-5f);
        inv2[r] = rsqrtf(q2 * (1.f / 640.f) + 1e-5f);
    }

    // ---- normalize + residual + store (channel-local) ----
    float w0 = __ldg(lnw + tid), w1 = __ldg(lnw + 128 + tid), w2 = __ldg(lnw + 256 + tid);
    float b0 = __ldg(lnb + tid);
#pragma unroll
    for (int r = 0; r < TR; r++) {
        int row = rowbase + r;
        if (row >= nrows) continue;
        size_t gb = (size_t)row * ROWLEN;
        out[gb + tid] = (fii[r][0] - mu[r]) * inv0[r] * w0 + b0 + __ldg(oldf + gb + tid);
#pragma unroll
        for (int i = 0; i < 3; i++) {
            size_t e = gb + 128 + tid * 3 + i;
            out[e] = fii[r][1 + i] * inv1[r] * w1 + __ldg(oldf + e);
        }
#pragma unroll
        for (int i = 0; i < 5; i++) {
            size_t e = gb + 512 + tid * 5 + i;
            out[e] = fii[r][4 + i] * inv2[r] * w2 + __ldg(oldf + e);
        }
    }
}

// ---------------------------------------------------------------------------
extern "C" void kernel_launch(void* const* d_in, const int* in_sizes, int n_in,
                              void* d_out, int out_size) {
    const float* x    = (const float*)d_in[0];
    const float* oldf = (const float*)d_in[1];
    const float* lw   = (const float*)d_in[2];
    const float* lb   = (const float*)d_in[3];
    const float* rw   = (const float*)d_in[4];
    const float* rb   = (const float*)d_in[5];
    const float* pwm  = (const float*)d_in[6];
    const float* pb   = (const float*)d_in[7];
    const float* tpw  = (const float*)d_in[8];
    const float* lnw  = (const float*)d_in[9];
    const float* lnb  = (const float*)d_in[10];
    float* out = (float*)d_out;

    int nrows = in_sizes[0] / ROWLEN;
    const int smem_bytes = (TR * PROW + 264 + 64) * sizeof(float);  // 23872 B

    cudaFuncSetAttribute(self_layer_kernel,
                         cudaFuncAttributeMaxDynamicSharedMemorySize, smem_bytes);

    w3j_init_kernel<<<1, 32>>>();

    int grid = (nrows + TR - 1) / TR;
    self_layer_kernel<<<grid, NT, smem_bytes>>>(x, oldf, lw, lb, rw, rb, pwm, pb,
                                                tpw, lnw, lnb, out, nrows);
}